// round 4
// baseline (speedup 1.0000x reference)
#include <cuda_runtime.h>

#define BINS 10

// Global scratch (no allocation allowed in kernel_launch).
__device__ float        g_sums[BINS];
__device__ unsigned int g_cnts[BINS];

__global__ void ghm_init() {
    int t = threadIdx.x;
    if (t < BINS) { g_sums[t] = 0.0f; g_cnts[t] = 0u; }
}

__global__ void __launch_bounds__(256)
ghm_pass(const float* __restrict__ x, const int* __restrict__ tg, int n) {
    __shared__ float    s_sum[BINS];
    __shared__ unsigned s_cnt[BINS];
    const int tid = threadIdx.x;
    if (tid < BINS) { s_sum[tid] = 0.0f; s_cnt[tid] = 0u; }
    __syncthreads();

    const unsigned lane = (unsigned)(tid & 31);
    unsigned myCnt = 0u;   // lanes 0..9 each accumulate the count for bin == lane

    const int n4     = n >> 2;
    const int idx    = blockIdx.x * 256 + tid;
    const int stride = gridDim.x * 256;
    const int iters  = (n4 + stride - 1) / stride;   // uniform across all threads
    const float4* __restrict__ x4 = (const float4*)x;
    const int4*   __restrict__ t4 = (const int4*)tg;

    for (int it = 0; it < iters; ++it) {
        const int  i     = idx + it * stride;
        const bool valid = (i < n4);
        float4 xv = make_float4(0.f, 0.f, 0.f, 0.f);
        int4   tv = make_int4(0, 0, 0, 0);
        if (valid) { xv = x4[i]; tv = t4[i]; }
        float xs[4] = {xv.x, xv.y, xv.z, xv.w};
        int   ts[4] = {tv.x, tv.y, tv.z, tv.w};

        #pragma unroll
        for (int j = 0; j < 4; ++j) {
            const float xx = xs[j];
            const float tf = (float)ts[j];
            const float ax = fabsf(xx);
            const float e  = __expf(-ax);                      // MUFU.EX2
            const float r  = __fdividef(1.0f, 1.0f + e);       // MUFU.RCP  (= sigmoid(|x|))
            const float s  = (xx >= 0.0f) ? r : (1.0f - r);    // sigmoid(x)
            const float gg = fabsf(s - tf);
            int bin = (int)(gg * 9.9999f);                     // floor(g*(BINS-1e-4)), g>=0
            bin = (bin > 9) ? 9 : bin;
            const int bkey = valid ? bin : 99;

            // Counts: warp-aggregated via ballot, banked into per-lane registers.
            #pragma unroll
            for (int b = 0; b < BINS; ++b) {
                unsigned m = __ballot_sync(0xffffffffu, bkey == b);
                if (lane == (unsigned)b) myCnt += (unsigned)__popc(m);
            }

            if (valid) {
                // ce = log(1+exp(x)) - x*t = max(x,0) - x*t + log1p(exp(-|x|))
                //    = max(x,0) - x*t - ln2*log2(r)
                const float ce = fmaxf(xx, 0.0f) - xx * tf
                               - 0.6931471805599453f * __log2f(r);  // MUFU.LG2
                atomicAdd(&s_sum[bin], ce);
            }
        }
    }

    if (lane < BINS) atomicAdd(&s_cnt[lane], myCnt);

    // Scalar tail for n % 4 (block 0 only).
    if (blockIdx.x == 0 && tid < (n & 3)) {
        const int i = (n & ~3) + tid;
        const float xx = x[i];
        const float tf = (float)tg[i];
        const float ax = fabsf(xx);
        const float e  = __expf(-ax);
        const float r  = __fdividef(1.0f, 1.0f + e);
        const float s  = (xx >= 0.0f) ? r : (1.0f - r);
        const float gg = fabsf(s - tf);
        int bin = (int)(gg * 9.9999f);
        bin = (bin > 9) ? 9 : bin;
        const float ce = fmaxf(xx, 0.0f) - xx * tf
                       - 0.6931471805599453f * __log2f(r);
        atomicAdd(&s_sum[bin], ce);
        atomicAdd(&s_cnt[bin], 1u);
    }
    __syncthreads();

    if (tid < BINS) {
        if (s_cnt[tid]) atomicAdd(&g_cnts[tid], s_cnt[tid]);
        atomicAdd(&g_sums[tid], s_sum[tid]);
    }
}

__global__ void ghm_final(float* __restrict__ out, int out_size) {
    const int lane = threadIdx.x;
    unsigned c = 0u;
    float ssum = 0.0f;
    if (lane < BINS) { c = g_cnts[lane]; ssum = g_sums[lane]; }
    const unsigned ne_mask = __ballot_sync(0xffffffffu, (lane < BINS) && (c > 0u));
    const float nonempty = (float)__popc(ne_mask);
    float term = 0.0f;
    if (lane < BINS) {
        const float gd = fmaxf((float)c * nonempty, 1e-6f);
        term = ssum / gd;   // mean(ce*w) = sum_b S_b / gd_b   (N cancels)
    }
    #pragma unroll
    for (int o = 16; o; o >>= 1) term += __shfl_xor_sync(0xffffffffu, term, o);
    for (int i = lane; i < out_size; i += 32) out[i] = term;
}

extern "C" void kernel_launch(void* const* d_in, const int* in_sizes, int n_in,
                              void* d_out, int out_size) {
    const float* x = (const float*)d_in[0];
    const int*   t = (const int*)d_in[1];
    const int n = in_sizes[0];
    ghm_init<<<1, 32>>>();
    ghm_pass<<<1184, 256>>>(x, t, n);
    ghm_final<<<1, 32>>>((float*)d_out, out_size);
}

// round 5
// speedup vs baseline: 5.0160x; 5.0160x over previous
#include <cuda_runtime.h>

#define BINS  10
#define GRID  444          // 148 SMs * 3 resident blocks
#define BLOCK 256

// Global scratch (zero-initialized at module load; reset by last block each run
// so the kernel is graph-replayable and deterministic).
__device__ float    g_sum[BINS];
__device__ float    g_cnt[BINS];
__device__ unsigned g_ticket;

__device__ __forceinline__ unsigned long long pack2(float lo, float hi) {
    unsigned long long v;
    asm("mov.b64 %0, {%1, %2};" : "=l"(v) : "f"(lo), "f"(hi));
    return v;
}
__device__ __forceinline__ void unpack2(unsigned long long v, float& lo, float& hi) {
    asm("mov.b64 {%0, %1}, %2;" : "=f"(lo), "=f"(hi) : "l"(v));
}

// Predicated packed accumulate: if (key == b) acc += (ce, 1.0f)
#define ACC_BIN(accv, key, b, ce1)                                             \
    asm volatile("{\n\t"                                                       \
                 ".reg .pred p;\n\t"                                           \
                 "setp.eq.s32 p, %1, %2;\n\t"                                  \
                 "@p add.rn.f32x2 %0, %0, %3;\n\t"                             \
                 "}"                                                           \
                 : "+l"(accv) : "r"(key), "r"(b), "l"(ce1))

__device__ __forceinline__ void ghm_elem(float xx, int tt, int keyofs,
                                         unsigned long long* acc) {
    // z = x if t==0 else -x  (sign-bit xor)
    const int   zi = __float_as_int(xx) ^ (tt << 31);
    const float z  = __int_as_float(zi);
    // a = exp(-|z|), r = sigmoid(|z|) = 1/(1+a)
    const float a = __expf(-fabsf(z));
    const float r = __fdividef(1.0f, 1.0f + a);
    // g = sigmoid(z) = |sigmoid(x) - t|
    const float g = (zi >= 0) ? r : (1.0f - r);
    // ce = softplus(z) = max(z,0) + log1p(a) = max(z,0) - ln2*log2(r)
    const float ce = fmaxf(z, 0.0f) - 0.69314718055994531f * __log2f(r);
    int bin = (int)(g * 9.9999f);
    bin = (bin > 9) ? 9 : bin;
    const int key = bin + keyofs;          // keyofs=64 for invalid lanes -> no match
    const unsigned long long ce1 = pack2(ce, 1.0f);
    #pragma unroll
    for (int b = 0; b < BINS; ++b) ACC_BIN(acc[b], key, b, ce1);
}

__global__ void __launch_bounds__(BLOCK, 3)
ghm_fused(const float* __restrict__ x, const int* __restrict__ tg, int n,
          float* __restrict__ out, int out_size) {
    const int tid = threadIdx.x;

    unsigned long long acc[BINS];
    #pragma unroll
    for (int b = 0; b < BINS; ++b) acc[b] = 0ULL;

    const int n4      = n >> 2;
    const int stride4 = GRID * BLOCK;            // float4-groups per k-slice
    const int idx     = blockIdx.x * BLOCK + tid;
    const int per_it  = 4 * stride4;             // groups consumed per outer iter
    const int iters   = (n4 + per_it - 1) / per_it;
    const float4* __restrict__ x4 = (const float4*)x;
    const int4*   __restrict__ t4 = (const int4*)tg;

    for (int it = 0; it < iters; ++it) {
        const int base = idx + it * per_it;
        float4 xv[4]; int4 tv[4]; int keyofs[4];
        // Front-batched loads (8 LDG.128 in flight) with clamped addresses —
        // no divergent loads; invalid lanes poisoned via keyofs.
        #pragma unroll
        for (int k = 0; k < 4; ++k) {
            int  gi = base + k * stride4;
            bool v  = (gi < n4);
            keyofs[k] = v ? 0 : 64;
            gi = v ? gi : 0;
            xv[k] = x4[gi];
            tv[k] = t4[gi];
        }
        #pragma unroll
        for (int k = 0; k < 4; ++k) {
            ghm_elem(xv[k].x, tv[k].x, keyofs[k], acc);
            ghm_elem(xv[k].y, tv[k].y, keyofs[k], acc);
            ghm_elem(xv[k].z, tv[k].z, keyofs[k], acc);
            ghm_elem(xv[k].w, tv[k].w, keyofs[k], acc);
        }
    }

    // Scalar tail (n % 4), block 0 only.
    const int rem = n & 3;
    if (blockIdx.x == 0 && tid < rem) {
        const int i = (n & ~3) + tid;
        ghm_elem(x[i], tg[i], 0, acc);
    }

    // Warp butterfly reduction of the 10 packed accumulators.
    #pragma unroll
    for (int b = 0; b < BINS; ++b) {
        #pragma unroll
        for (int o = 16; o; o >>= 1) {
            float lo, hi;
            unpack2(acc[b], lo, hi);
            const float lo2 = __shfl_xor_sync(0xffffffffu, lo, o);
            const float hi2 = __shfl_xor_sync(0xffffffffu, hi, o);
            const unsigned long long other = pack2(lo2, hi2);
            asm("add.rn.f32x2 %0, %0, %1;" : "+l"(acc[b]) : "l"(other));
        }
    }

    // Block reduction: warp leaders -> shared, then to global.
    __shared__ float sh_sum[BINS], sh_cnt[BINS];
    __shared__ bool  s_last;
    if (tid < BINS) { sh_sum[tid] = 0.0f; sh_cnt[tid] = 0.0f; }
    __syncthreads();
    if ((tid & 31) == 0) {
        #pragma unroll
        for (int b = 0; b < BINS; ++b) {
            float lo, hi;
            unpack2(acc[b], lo, hi);
            atomicAdd(&sh_sum[b], lo);
            atomicAdd(&sh_cnt[b], hi);
        }
    }
    __syncthreads();
    if (tid < BINS) {
        atomicAdd(&g_sum[tid], sh_sum[tid]);
        atomicAdd(&g_cnt[tid], sh_cnt[tid]);
    }

    // Last-block-done: finalize + reset scratch for the next graph replay.
    __threadfence();
    if (tid == 0) {
        const unsigned t = atomicAdd(&g_ticket, 1u);
        s_last = (t == (unsigned)(GRID - 1));
    }
    __syncthreads();
    if (s_last && tid < 32) {
        float c = 0.0f, ssum = 0.0f;
        if (tid < BINS) {
            c    = atomicAdd(&g_cnt[tid], 0.0f);   // coherent L2 read
            ssum = atomicAdd(&g_sum[tid], 0.0f);
        }
        const unsigned ne = __ballot_sync(0xffffffffu, (tid < BINS) && (c > 0.0f));
        const float nonempty = (float)__popc(ne);
        float term = 0.0f;
        if (tid < BINS)
            term = ssum / fmaxf(c * nonempty, 1e-6f);  // mean(ce*w) = sum_b S_b/gd_b
        #pragma unroll
        for (int o = 16; o; o >>= 1)
            term += __shfl_xor_sync(0xffffffffu, term, o);
        for (int i = tid; i < out_size; i += 32) out[i] = term;
        // Reset for next replay.
        if (tid < BINS) { g_sum[tid] = 0.0f; g_cnt[tid] = 0.0f; }
        if (tid == 0) g_ticket = 0u;
    }
}

extern "C" void kernel_launch(void* const* d_in, const int* in_sizes, int n_in,
                              void* d_out, int out_size) {
    const float* x = (const float*)d_in[0];
    const int*   t = (const int*)d_in[1];
    const int n = in_sizes[0];
    ghm_fused<<<GRID, BLOCK>>>(x, t, n, (float*)d_out, out_size);
}

// round 6
// speedup vs baseline: 7.7543x; 1.5459x over previous
#include <cuda_runtime.h>

#define BINS  10
#define ROWW  11            // float2 per thread row: 10 bins + 1 pad (also kills bank conflicts)
#define BLOCK 256
#define OCC   4
#define GRID  (148 * OCC)

// Global scratch (zero at module load; reset by last block each run -> graph-replayable).
__device__ float    g_sum[BINS];
__device__ float    g_cnt[BINS];
__device__ unsigned g_ticket;

__device__ __forceinline__ void ghm_elem(float xx, int tt, float2* __restrict__ row) {
    // z = x if t==0 else -x  (sign-bit xor). Then g = sigmoid(z), ce = softplus(z).
    const int   zi = __float_as_int(xx) ^ (tt << 31);
    const float z  = __int_as_float(zi);
    const float a  = __expf(-fabsf(z));          // MUFU.EX2
    const float p  = 1.0f + a;
    const float r  = __fdividef(1.0f, p);        // MUFU.RCP  (= sigmoid(|z|))
    const float g  = (zi >= 0) ? r : (1.0f - r); // sigmoid(z) = |sigmoid(x)-t|
    // ce = max(z,0) + log1p(a) = max(z,0) + ln2*log2(1+a)
    const float ce = fmaxf(z, 0.0f) + 0.69314718055994531f * __log2f(p); // MUFU.LG2
    const int bin  = (int)(g * 9.9999f);         // g < 1 strictly -> bin in [0,9]
    float2 v = row[bin];                         // LDS.64
    v.x += ce;
    v.y += 1.0f;
    row[bin] = v;                                // STS.64
}

__global__ void __launch_bounds__(BLOCK, OCC)
ghm_fused(const float* __restrict__ x, const int* __restrict__ tg, int n,
          float* __restrict__ out, int out_size) {
    __shared__ float2 rows[BLOCK][ROWW];
    __shared__ float  sh_fin[2 * BINS];
    __shared__ bool   s_last;

    const int tid = threadIdx.x;
    float2* __restrict__ row = rows[tid];
    #pragma unroll
    for (int b = 0; b < ROWW; ++b) row[b] = make_float2(0.0f, 0.0f);

    const int n4      = n >> 2;
    const int stride4 = GRID * BLOCK;
    const int idx     = blockIdx.x * BLOCK + tid;
    const int per_it  = 4 * stride4;          // float4-groups per super-iteration
    const int full    = n4 / per_it;          // fully-valid super-iterations (uniform)
    const float4* __restrict__ x4 = (const float4*)x;
    const int4*   __restrict__ t4 = (const int4*)tg;

    // Hot loop: 16 elems/thread/iter, 8 front-batched LDG.128, zero validity logic.
    for (int it = 0; it < full; ++it) {
        const int base = idx + it * per_it;
        float4 xv[4]; int4 tv[4];
        #pragma unroll
        for (int k = 0; k < 4; ++k) {
            xv[k] = x4[base + k * stride4];
            tv[k] = t4[base + k * stride4];
        }
        #pragma unroll
        for (int k = 0; k < 4; ++k) {
            ghm_elem(xv[k].x, tv[k].x, row);
            ghm_elem(xv[k].y, tv[k].y, row);
            ghm_elem(xv[k].z, tv[k].z, row);
            ghm_elem(xv[k].w, tv[k].w, row);
        }
    }

    // Ragged float4 tail (no warp collectives in flight -> divergence is fine).
    for (int i = idx + full * per_it; i < n4; i += stride4) {
        const float4 xv = x4[i];
        const int4   tv = t4[i];
        ghm_elem(xv.x, tv.x, row);
        ghm_elem(xv.y, tv.y, row);
        ghm_elem(xv.z, tv.z, row);
        ghm_elem(xv.w, tv.w, row);
    }

    // Scalar tail (n % 4), block 0 only.
    if (blockIdx.x == 0 && tid < (n & 3)) {
        const int i = (n & ~3) + tid;
        ghm_elem(x[i], tg[i], row);
    }

    // ── Reduction: own smem row -> regs -> warp butterfly -> block -> global ──
    float sums[BINS], cnts[BINS];
    #pragma unroll
    for (int b = 0; b < BINS; ++b) {
        const float2 v = row[b];
        sums[b] = v.x; cnts[b] = v.y;
    }
    #pragma unroll
    for (int b = 0; b < BINS; ++b) {
        #pragma unroll
        for (int o = 16; o; o >>= 1) {
            sums[b] += __shfl_xor_sync(0xffffffffu, sums[b], o);
            cnts[b] += __shfl_xor_sync(0xffffffffu, cnts[b], o);
        }
    }
    if (tid < 2 * BINS) sh_fin[tid] = 0.0f;
    __syncthreads();
    if ((tid & 31) == 0) {
        #pragma unroll
        for (int b = 0; b < BINS; ++b) {
            atomicAdd(&sh_fin[b], sums[b]);
            atomicAdd(&sh_fin[BINS + b], cnts[b]);
        }
    }
    __syncthreads();
    if (tid < BINS) {
        atomicAdd(&g_sum[tid], sh_fin[tid]);
        atomicAdd(&g_cnt[tid], sh_fin[BINS + tid]);
    }

    // Last-block ticket: finalize + reset scratch for next graph replay.
    __threadfence();
    if (tid == 0) {
        const unsigned t = atomicAdd(&g_ticket, 1u);
        s_last = (t == (unsigned)(GRID - 1));
    }
    __syncthreads();
    if (s_last && tid < 32) {
        float c = 0.0f, ssum = 0.0f;
        if (tid < BINS) {
            c    = atomicAdd(&g_cnt[tid], 0.0f);   // coherent L2 read
            ssum = atomicAdd(&g_sum[tid], 0.0f);
        }
        const unsigned ne = __ballot_sync(0xffffffffu, (tid < BINS) && (c > 0.0f));
        const float nonempty = (float)__popc(ne);
        float term = 0.0f;
        if (tid < BINS)
            term = ssum / fmaxf(c * nonempty, 1e-6f);  // mean(ce*w) = sum_b S_b/gd_b
        #pragma unroll
        for (int o = 16; o; o >>= 1)
            term += __shfl_xor_sync(0xffffffffu, term, o);
        for (int i = tid; i < out_size; i += 32) out[i] = term;
        if (tid < BINS) { g_sum[tid] = 0.0f; g_cnt[tid] = 0.0f; }
        if (tid == 0) g_ticket = 0u;
    }
}

extern "C" void kernel_launch(void* const* d_in, const int* in_sizes, int n_in,
                              void* d_out, int out_size) {
    const float* x = (const float*)d_in[0];
    const int*   t = (const int*)d_in[1];
    const int n = in_sizes[0];
    ghm_fused<<<GRID, BLOCK>>>(x, t, n, (float*)d_out, out_size);
}